// round 4
// baseline (speedup 1.0000x reference)
#include <cuda_runtime.h>
#include <math.h>

#define Nn 100000
#define Ee 3200000
#define Ff 128
#define Hh 16
#define Cc 10
#define Kk1 25000
#define Kk2 6250
#define C2S 16

// ---------------- scratch ------------------------------------------------------
__device__ __align__(16) float d_h0[Nn * Hh];
__device__ __align__(16) float d_h[Nn * Hh];
__device__ float d_dinv[Nn];
__device__ float d_t[Nn];
__device__ float d_score[Nn];
__device__ unsigned long long d_key[Nn];
__device__ int d_perm[Kk1];
__device__ int d_newidx[Nn];
__device__ int d_deg[Nn];
__device__ int d_off[Nn + 1];
__device__ int d_cur[Nn];
__device__ int d_col[Ee];
__device__ __align__(16) float d_x1[Kk1 * Hh];
__device__ __align__(16) float d_g0[Kk1 * C2S];
__device__ __align__(16) float d_h2[Kk1 * C2S];
__device__ float d_dinv2[Kk1];
__device__ float d_t2[Kk1];
__device__ float d_score2[Kk1];
__device__ unsigned int d_hist[8192];
__device__ unsigned long long d_prefix;
__device__ int d_remk;
__device__ int d_counter;
__device__ unsigned int d_tick;

// ---------------- init ---------------------------------------------------------
__global__ void k_init() {
    int i = blockIdx.x * blockDim.x + threadIdx.x;
    if (i < Nn) { d_deg[i] = 0; d_newidx[i] = -1; }
}

// ---------------- fused: h0 = x @ W1 (warp/node)  ||  deg count -----------------
#define MM1_BLOCKS 12500
#define DEG_BLOCKS 12500
__global__ void k_front(const float* __restrict__ x, const float* __restrict__ W1,
                        const int* __restrict__ dst) {
    if (blockIdx.x < MM1_BLOCKS) {
        __shared__ float Ws[Ff * Hh];
        for (int i = threadIdx.x; i < Ff * Hh; i += blockDim.x) Ws[i] = W1[i];
        __syncthreads();
        int node = blockIdx.x * 8 + (threadIdx.x >> 5);
        int lane = threadIdx.x & 31;
        const float* xr = x + (size_t)node * Ff;
        float acc[Hh];
#pragma unroll
        for (int j = 0; j < Hh; j++) acc[j] = 0.f;
#pragma unroll
        for (int c = 0; c < 4; c++) {
            int f = c * 32 + lane;
            float xv = xr[f];
            const float* wr = Ws + f * Hh;
#pragma unroll
            for (int j = 0; j < Hh; j++) acc[j] += xv * wr[j];
        }
#pragma unroll
        for (int off = 16; off; off >>= 1)
#pragma unroll
            for (int j = 0; j < Hh; j++) acc[j] += __shfl_xor_sync(0xFFFFFFFFu, acc[j], off);
        if (lane < Hh) d_h0[(size_t)node * Hh + lane] = acc[lane];
    } else {
        int e = (blockIdx.x - MM1_BLOCKS) * 256 + threadIdx.x;
        atomicAdd(&d_deg[dst[e]], 1);
    }
}

// ---------------- offsets: exclusive scan + dinv (1 block, 1024 thr) ------------
__global__ void k_offsets() {
    const int T = 1024;
    const int CH = (Nn + T - 1) / T;   // 98
    int t = threadIdx.x;
    int lo = t * CH, hi = min(lo + CH, Nn);
    int s = 0;
    for (int i = lo; i < hi; i++) s += d_deg[i];
    __shared__ int ws[32];
    int lane = t & 31, wid = t >> 5;
    int v = s;
#pragma unroll
    for (int o = 1; o < 32; o <<= 1) {
        int u = __shfl_up_sync(0xFFFFFFFFu, v, o);
        if (lane >= o) v += u;
    }
    if (lane == 31) ws[wid] = v;
    __syncthreads();
    if (wid == 0) {
        int u = ws[lane];
#pragma unroll
        for (int o = 1; o < 32; o <<= 1) {
            int y = __shfl_up_sync(0xFFFFFFFFu, u, o);
            if (lane >= o) u += y;
        }
        ws[lane] = u;
    }
    __syncthreads();
    int run = v - s + (wid > 0 ? ws[wid - 1] : 0);
    for (int i = lo; i < hi; i++) {
        int c = d_deg[i];
        d_off[i] = run;
        d_cur[i] = run;
        d_dinv[i] = rsqrtf((float)c + 1.0f);
        run += c;
    }
    if (t == T - 1) d_off[Nn] = Ee;
}

__global__ void k_buildcsr(const int* __restrict__ src, const int* __restrict__ dst) {
    int e = blockIdx.x * blockDim.x + threadIdx.x;
    if (e >= Ee) return;
    int pos = atomicAdd(&d_cur[dst[e]], 1);
    d_col[pos] = src[e];
}

// ---------------- conv1 gather + self-loop + bias + relu + score dots ----------
__global__ void k_gather1(const float* __restrict__ b1, const float* __restrict__ wroot,
                          const float* __restrict__ wrel, const float* __restrict__ pb) {
    int node = blockIdx.x * 8 + (threadIdx.x >> 5);
    int lane = threadIdx.x & 31;
    int base = d_off[node], deg = d_off[node + 1] - base;
    int q = lane & 3;
    float4 acc = make_float4(0.f, 0.f, 0.f, 0.f);
    for (int j = (lane >> 2); j < deg; j += 8) {
        int s = __ldg(&d_col[base + j]);
        float w = __ldg(&d_dinv[s]);
        float4 v = *(const float4*)&d_h0[s * Hh + q * 4];
        acc.x += v.x * w; acc.y += v.y * w; acc.z += v.z * w; acc.w += v.w * w;
    }
#pragma unroll
    for (int o = 4; o < 32; o <<= 1) {
        acc.x += __shfl_xor_sync(0xFFFFFFFFu, acc.x, o);
        acc.y += __shfl_xor_sync(0xFFFFFFFFu, acc.y, o);
        acc.z += __shfl_xor_sync(0xFFFFFFFFu, acc.z, o);
        acc.w += __shfl_xor_sync(0xFFFFFFFFu, acc.w, o);
    }
    float di = d_dinv[node];
    float sr = 0.f, st = 0.f;
    if (lane < 4) {
        float4 self = *(const float4*)&d_h0[node * Hh + q * 4];
        float s2 = di * di;
        float4 b = __ldg(&((const float4*)b1)[q]);
        float4 r;
        r.x = fmaxf(acc.x * di + self.x * s2 + b.x, 0.f);
        r.y = fmaxf(acc.y * di + self.y * s2 + b.y, 0.f);
        r.z = fmaxf(acc.z * di + self.z * s2 + b.z, 0.f);
        r.w = fmaxf(acc.w * di + self.w * s2 + b.w, 0.f);
        *(float4*)&d_h[node * Hh + q * 4] = r;
        float4 wr = __ldg(&((const float4*)wroot)[q]);
        float4 wl = __ldg(&((const float4*)wrel)[q]);
        sr = r.x * wr.x + r.y * wr.y + r.z * wr.z + r.w * wr.w;
        st = r.x * wl.x + r.y * wl.y + r.z * wl.z + r.w * wl.w;
    }
    sr += __shfl_xor_sync(0xFFFFFFFFu, sr, 1);
    sr += __shfl_xor_sync(0xFFFFFFFFu, sr, 2);
    st += __shfl_xor_sync(0xFFFFFFFFu, st, 1);
    st += __shfl_xor_sync(0xFFFFFFFFu, st, 2);
    if (lane == 0) {
        d_score[node] = sr + __ldg(&pb[0]);
        d_t[node] = st;
    }
}

// score aggregation: score[i] += sum_{src in-edges} t[src]
__global__ void k_scats1g() {
    int node = blockIdx.x * 8 + (threadIdx.x >> 5);
    int lane = threadIdx.x & 31;
    int base = d_off[node], deg = d_off[node + 1] - base;
    float s = 0.f;
    for (int j = lane; j < deg; j += 32)
        s += __ldg(&d_t[__ldg(&d_col[base + j])]);
#pragma unroll
    for (int o = 16; o; o >>= 1) s += __shfl_xor_sync(0xFFFFFFFFu, s, o);
    if (lane == 0) d_score[node] += s;
}

// ---------------- radix select: 13-bit digits, fused hist+scan ------------------
__device__ __forceinline__ unsigned f2u(float f) {
    unsigned u = __float_as_uint(f);
    return (u & 0x80000000u) ? ~u : (u | 0x80000000u);
}

// which 0: d_score, key = f2u<<17 | (131071-i). which 1: d_score2, f2u<<15 | (32767-i)
template <bool FIRST>
__global__ void k_pass(int n, int shift, int w, int k, int which) {
    __shared__ unsigned sh[8192];
    int nb = 1 << w;
    for (int b = threadIdx.x; b < nb; b += blockDim.x) sh[b] = 0;
    __syncthreads();
    unsigned mask = (unsigned)(nb - 1);
    unsigned long long pre = FIRST ? 0ull : d_prefix;
    for (int i = blockIdx.x * blockDim.x + threadIdx.x; i < n; i += gridDim.x * blockDim.x) {
        unsigned long long key;
        if (FIRST) {
            if (which) key = ((unsigned long long)f2u(d_score2[i]) << 15) |
                             (unsigned long long)(32767u - (unsigned)i);
            else       key = ((unsigned long long)f2u(d_score[i]) << 17) |
                             (unsigned long long)(131071u - (unsigned)i);
            d_key[i] = key;
        } else {
            key = d_key[i];
        }
        bool ok = FIRST || ((key >> (shift + w)) == pre);
        if (ok) atomicAdd(&sh[(unsigned)(key >> shift) & mask], 1u);
    }
    __syncthreads();
    for (int b = threadIdx.x; b < nb; b += blockDim.x)
        if (sh[b]) atomicAdd(&d_hist[b], sh[b]);
    __threadfence();
    __shared__ bool last;
    if (threadIdx.x == 0) last = (atomicAdd(&d_tick, 1u) == (unsigned)gridDim.x - 1u);
    __syncthreads();
    if (!last) return;

    for (int b = threadIdx.x; b < nb; b += blockDim.x) sh[b] = d_hist[b];
    __syncthreads();
    __shared__ unsigned part[256];
    __shared__ int tstar;
    __shared__ unsigned cumsh;
    int seg = nb >> 8;
    int base = threadIdx.x * seg;
    unsigned s = 0;
    for (int v = 0; v < seg; v++) s += sh[base + v];
    part[threadIdx.x] = s;
    __syncthreads();
    if (threadIdx.x == 0) {
        int rem = FIRST ? k : d_remk;
        unsigned cum = 0;
        int t;
        for (t = 255; t >= 0; t--) {
            if (cum + part[t] >= (unsigned)rem) break;
            cum += part[t];
        }
        tstar = t; cumsh = cum;
    }
    __syncthreads();
    if (threadIdx.x == tstar) {
        unsigned cum = cumsh;
        int rem = FIRST ? k : d_remk;
        for (int v = seg - 1; v >= 0; v--) {
            unsigned c = sh[base + v];
            cum += c;
            if (cum >= (unsigned)rem) {
                unsigned digit = (unsigned)(base + v);
                d_prefix = FIRST ? (unsigned long long)digit
                                 : ((d_prefix << w) | (unsigned long long)digit);
                d_remk = rem - (int)(cum - c);
                break;
            }
        }
        d_counter = 0;
        d_tick = 0;
    }
    __syncthreads();
    for (int b = threadIdx.x; b < nb; b += blockDim.x) d_hist[b] = 0;
}

// pool1: select + setperm + gather fused
__global__ void k_selgsp() {
    int i = blockIdx.x * blockDim.x + threadIdx.x;
    if (i >= Nn) return;
    if (d_key[i] >= d_prefix) {
        int p = atomicAdd(&d_counter, 1);
        d_perm[p] = i;
        d_newidx[i] = p;
        float th = tanhf(d_score[i]);
        const float4* h = (const float4*)&d_h[i * Hh];
        float4* o = (float4*)&d_x1[p * Hh];
#pragma unroll
        for (int q = 0; q < 4; q++) {
            float4 v = h[q];
            v.x *= th; v.y *= th; v.z *= th; v.w *= th;
            o[q] = v;
        }
    }
}

__global__ void k_select2() {
    int i = blockIdx.x * blockDim.x + threadIdx.x;
    if (i >= Kk1) return;
    if (d_key[i] >= d_prefix) {
        int p = atomicAdd(&d_counter, 1);
        d_perm[p] = i;
    }
}

// ---------------- conv2 phase A: deg2 + dinv2 + g0 + self-loop init -------------
__global__ void k_conv2a(const float* __restrict__ W2, const float* __restrict__ b2) {
    int p = blockIdx.x * 8 + (threadIdx.x >> 5);
    int lane = threadIdx.x & 31;
    if (p >= Kk1) return;
    int i = d_perm[p];
    int base = d_off[i], deg = d_off[i + 1] - base;
    int cnt = 0;
    for (int j = lane; j < deg; j += 32)
        cnt += (__ldg(&d_newidx[__ldg(&d_col[base + j])]) >= 0);
#pragma unroll
    for (int o = 16; o; o >>= 1) cnt += __shfl_xor_sync(0xFFFFFFFFu, cnt, o);
    float di = rsqrtf((float)cnt + 1.0f);
    if (lane == 0) d_dinv2[p] = di;
    float g = 0.f;
    if (lane < Cc) {
#pragma unroll
        for (int f = 0; f < Hh; f++)
            g += __ldg(&d_x1[p * Hh + f]) * __ldg(&W2[f * Cc + lane]);
    }
    if (lane < C2S) {
        float gv = (lane < Cc) ? g : 0.f;
        d_g0[p * C2S + lane] = gv;
        d_h2[p * C2S + lane] = (lane < Cc) ? (g * di * di + __ldg(&b2[lane])) : 0.f;
    }
}

// conv2 phase B: gather valid neighbors + finalize h2 + score dots ---------------
__global__ void k_gather2(const float* __restrict__ wroot, const float* __restrict__ wrel,
                          const float* __restrict__ pb) {
    int p = blockIdx.x * 8 + (threadIdx.x >> 5);
    int lane = threadIdx.x & 31;
    if (p >= Kk1) return;
    int i = d_perm[p];
    int base = d_off[i], deg = d_off[i + 1] - base;
    float acc[Cc];
#pragma unroll
    for (int c = 0; c < Cc; c++) acc[c] = 0.f;
    for (int j = lane; j < deg; j += 32) {
        int ns = __ldg(&d_newidx[__ldg(&d_col[base + j])]);
        if (ns >= 0) {
            float w = __ldg(&d_dinv2[ns]);
            const float* gr = &d_g0[ns * C2S];
#pragma unroll
            for (int c = 0; c < Cc; c++) acc[c] += __ldg(&gr[c]) * w;
        }
    }
#pragma unroll
    for (int o = 16; o; o >>= 1)
#pragma unroll
        for (int c = 0; c < Cc; c++) acc[c] += __shfl_xor_sync(0xFFFFFFFFu, acc[c], o);
    if (lane == 0) {
        float di = d_dinv2[p];
        float sr = 0.f, st = 0.f;
#pragma unroll
        for (int c = 0; c < Cc; c++) {
            float v = d_h2[p * C2S + c] + acc[c] * di;
            d_h2[p * C2S + c] = v;
            sr += v * __ldg(&wroot[c]);
            st += v * __ldg(&wrel[c]);
        }
        d_score2[p] = sr + __ldg(&pb[0]);
        d_t2[p] = st;
    }
}

__global__ void k_scats2g() {
    int p = blockIdx.x * 8 + (threadIdx.x >> 5);
    int lane = threadIdx.x & 31;
    if (p >= Kk1) return;
    int i = d_perm[p];
    int base = d_off[i], deg = d_off[i + 1] - base;
    float s = 0.f;
    for (int j = lane; j < deg; j += 32) {
        int ns = __ldg(&d_newidx[__ldg(&d_col[base + j])]);
        if (ns >= 0) s += __ldg(&d_t2[ns]);
    }
#pragma unroll
    for (int o = 16; o; o >>= 1) s += __shfl_xor_sync(0xFFFFFFFFu, s, o);
    if (lane == 0) d_score2[p] += s;
}

// ---------------- final --------------------------------------------------------
__global__ void k_reduce(float* __restrict__ out) {
    float acc[Cc];
#pragma unroll
    for (int j = 0; j < Cc; j++) acc[j] = 0.f;
    for (int p = threadIdx.x; p < Kk2; p += 256) {
        int i = d_perm[p];
        float th = tanhf(d_score2[i]);
#pragma unroll
        for (int j = 0; j < Cc; j++) acc[j] += d_h2[i * C2S + j] * th;
    }
#pragma unroll
    for (int off = 16; off; off >>= 1)
#pragma unroll
        for (int j = 0; j < Cc; j++) acc[j] += __shfl_xor_sync(0xFFFFFFFFu, acc[j], off);
    __shared__ float sh[8][Cc];
    int w = threadIdx.x >> 5, l = threadIdx.x & 31;
    if (l == 0)
#pragma unroll
        for (int j = 0; j < Cc; j++) sh[w][j] = acc[j];
    __syncthreads();
    if (threadIdx.x == 0) {
        float m[Cc], mx = -1e30f;
#pragma unroll
        for (int j = 0; j < Cc; j++) {
            float s = 0.f;
            for (int ww = 0; ww < 8; ww++) s += sh[ww][j];
            m[j] = s / (float)Kk2;
            mx = fmaxf(mx, m[j]);
        }
        float lse = 0.f;
#pragma unroll
        for (int j = 0; j < Cc; j++) lse += expf(m[j] - mx);
        lse = logf(lse);
#pragma unroll
        for (int j = 0; j < Cc; j++) out[j] = m[j] - mx - lse;
    }
}

// ---------------- launch --------------------------------------------------------
extern "C" void kernel_launch(void* const* d_in, const int* in_sizes, int n_in,
                              void* d_out, int out_size) {
    const float* x = (const float*)d_in[0];
    const int* esrc = (const int*)d_in[1];
    const int* edst = (const int*)d_in[2];
    const float* W1 = (const float*)d_in[3];
    const float* b1 = (const float*)d_in[4];
    const float* p1wr = (const float*)d_in[5];
    const float* p1wl = (const float*)d_in[6];
    const float* p1b = (const float*)d_in[7];
    const float* W2 = (const float*)d_in[8];
    const float* b2 = (const float*)d_in[9];
    const float* p2wr = (const float*)d_in[10];
    const float* p2wl = (const float*)d_in[11];
    const float* p2b = (const float*)d_in[12];
    float* out = (float*)d_out;

    const int T = 256;
    k_init<<<(Nn + T - 1) / T, T>>>();
    k_front<<<MM1_BLOCKS + DEG_BLOCKS, T>>>(x, W1, edst);
    k_offsets<<<1, 1024>>>();
    k_buildcsr<<<(Ee + T - 1) / T, T>>>(esrc, edst);
    k_gather1<<<Nn / 8, T>>>(b1, p1wr, p1wl, p1b);
    k_scats1g<<<Nn / 8, T>>>();

    // pool1 top-k over 49-bit keys: (36,13)(23,13)(10,13)(0,10)
    k_pass<true><<<148, 256>>>(Nn, 36, 13, Kk1, 0);
    k_pass<false><<<148, 256>>>(Nn, 23, 13, Kk1, 0);
    k_pass<false><<<148, 256>>>(Nn, 10, 13, Kk1, 0);
    k_pass<false><<<148, 256>>>(Nn, 0, 10, Kk1, 0);
    k_selgsp<<<(Nn + T - 1) / T, T>>>();

    k_conv2a<<<(Kk1 + 7) / 8, T>>>(W2, b2);
    k_gather2<<<(Kk1 + 7) / 8, T>>>(p2wr, p2wl, p2b);
    k_scats2g<<<(Kk1 + 7) / 8, T>>>();

    // pool2 top-k over 47-bit keys: (34,13)(21,13)(8,13)(0,8)
    k_pass<true><<<37, 256>>>(Kk1, 34, 13, Kk2, 1);
    k_pass<false><<<37, 256>>>(Kk1, 21, 13, Kk2, 1);
    k_pass<false><<<37, 256>>>(Kk1, 8, 13, Kk2, 1);
    k_pass<false><<<37, 256>>>(Kk1, 0, 8, Kk2, 1);
    k_select2<<<(Kk1 + T - 1) / T, T>>>();

    k_reduce<<<1, 256>>>(out);
}

// round 5
// speedup vs baseline: 1.7351x; 1.7351x over previous
#include <cuda_runtime.h>
#include <math.h>

#define Nn 100000
#define Ee 3200000
#define Ff 128
#define Hh 16
#define Cc 10
#define Kk1 25000
#define Kk2 6250
#define G1 64     // topk1 persistent grid
#define G2 32     // topk2 persistent grid

// ---------------- scratch ------------------------------------------------------
__device__ __align__(16) float d_h0[Nn * Hh];   // x@W1, then scaled by dinv
__device__ __align__(16) float d_h[Nn * Hh];    // conv1 edge accumulator -> relu(h)
__device__ float d_dinv[Nn];
__device__ int d_deg[Nn];
__device__ float d_t[Nn];
__device__ float d_score[Nn];
__device__ unsigned long long d_key[Nn];
__device__ int d_perm[Kk1];
__device__ unsigned d_selbit[3136];             // selection bitmask (12.5KB)
__device__ int d_deg2[Nn];
__device__ float d_dinv2[Nn];
__device__ __align__(16) float d_x1[Kk1 * Hh];
__device__ __align__(16) float d_g0[Nn * 16];   // old-id indexed, padded
__device__ __align__(16) float d_h2[Nn * 16];
__device__ float d_t2[Nn];
__device__ float d_score2[Nn];
__device__ unsigned d_hist1[4][8192];
__device__ unsigned d_hist2[4][8192];
__device__ unsigned d_bar1, d_bar2, d_tick2;
__device__ int d_counter;
__device__ float d_acc[Cc];

__device__ __forceinline__ void red_v4(float* p, float4 v) {
    asm volatile("red.global.add.v4.f32 [%0], {%1,%2,%3,%4};"
                 :: "l"(p), "f"(v.x), "f"(v.y), "f"(v.z), "f"(v.w) : "memory");
}
__device__ __forceinline__ unsigned f2u(float f) {
    unsigned u = __float_as_uint(f);
    return (u & 0x80000000u) ? ~u : (u | 0x80000000u);
}

// ---------------- init: zero all accumulators / state --------------------------
__global__ void k_init() {
    int i = blockIdx.x * blockDim.x + threadIdx.x;
    if (i < Nn * Hh) d_h[i] = 0.f;
    if (i < Nn) d_deg[i] = 0;
    if (i < 3136) d_selbit[i] = 0;
    if (i < 32768) { ((unsigned*)d_hist1)[i] = 0; ((unsigned*)d_hist2)[i] = 0; }
    if (i < Cc) d_acc[i] = 0.f;
    if (i == 0) { d_bar1 = 0; d_bar2 = 0; d_tick2 = 0; d_counter = 0; }
}

// ---------------- fused: h0 = x @ W1 (grid-stride warps)  ||  deg count --------
#define MM1_BLOCKS 1536
#define DEG_BLOCKS 1024
__global__ void k_front(const float* __restrict__ x, const float* __restrict__ W1,
                        const int* __restrict__ dst) {
    if (blockIdx.x < MM1_BLOCKS) {
        __shared__ float Ws[Ff * Hh];
        for (int i = threadIdx.x; i < Ff * Hh; i += blockDim.x) Ws[i] = W1[i];
        __syncthreads();
        int lane = threadIdx.x & 31;
        for (int node = blockIdx.x * 8 + (threadIdx.x >> 5); node < Nn;
             node += MM1_BLOCKS * 8) {
            const float* xr = x + (size_t)node * Ff;
            float acc[Hh];
#pragma unroll
            for (int j = 0; j < Hh; j++) acc[j] = 0.f;
#pragma unroll
            for (int c = 0; c < 4; c++) {
                int f = c * 32 + lane;
                float xv = xr[f];
                const float* wr = Ws + f * Hh;
#pragma unroll
                for (int j = 0; j < Hh; j++) acc[j] += xv * wr[j];
            }
#pragma unroll
            for (int off = 16; off; off >>= 1)
#pragma unroll
                for (int j = 0; j < Hh; j++)
                    acc[j] += __shfl_xor_sync(0xFFFFFFFFu, acc[j], off);
            if (lane < Hh) d_h0[(size_t)node * Hh + lane] = acc[lane];
        }
    } else {
        for (int e = (blockIdx.x - MM1_BLOCKS) * 256 + threadIdx.x; e < Ee;
             e += DEG_BLOCKS * 256)
            atomicAdd(&d_deg[dst[e]], 1);
    }
}

// dinv + pre-scale h0 by dinv (so scat1 needs no dinv reads)
__global__ void k_dinv() {
    int i = blockIdx.x * blockDim.x + threadIdx.x;
    if (i >= Nn) return;
    float di = rsqrtf((float)d_deg[i] + 1.0f);
    d_dinv[i] = di;
    float4* h0 = (float4*)&d_h0[i * Hh];
#pragma unroll
    for (int q = 0; q < 4; q++) {
        float4 v = h0[q];
        v.x *= di; v.y *= di; v.z *= di; v.w *= di;
        h0[q] = v;
    }
}

// edge scatter: 4 threads/edge, one v4 red each (accumulator pre-zeroed)
__global__ void k_scat1(const int* __restrict__ src, const int* __restrict__ dst) {
    int t = blockIdx.x * blockDim.x + threadIdx.x;
    int e = t >> 2, q = t & 3;
    int s = src[e], d = dst[e];
    float4 v = *(const float4*)&d_h0[s * Hh + q * 4];
    red_v4(&d_h[d * Hh + q * 4], v);
}

// finalize conv1: h = relu(acc*dinv + h0s*dinv + b)  (h0s = h0*dinv already)
__global__ void k_prep1(const float* __restrict__ b1, const float* __restrict__ wroot,
                        const float* __restrict__ wrel, const float* __restrict__ pb) {
    int i = blockIdx.x * blockDim.x + threadIdx.x;
    if (i >= Nn) return;
    float di = d_dinv[i];
    float4* h = (float4*)&d_h[i * Hh];
    const float4* h0 = (const float4*)&d_h0[i * Hh];
    float sr = 0.f, st = 0.f;
#pragma unroll
    for (int q = 0; q < 4; q++) {
        float4 a = h[q], s0 = h0[q];
        float4 b = __ldg(&((const float4*)b1)[q]);
        float4 r;
        r.x = fmaxf((a.x + s0.x) * di + b.x, 0.f);
        r.y = fmaxf((a.y + s0.y) * di + b.y, 0.f);
        r.z = fmaxf((a.z + s0.z) * di + b.z, 0.f);
        r.w = fmaxf((a.w + s0.w) * di + b.w, 0.f);
        h[q] = r;
        float4 wr = __ldg(&((const float4*)wroot)[q]);
        float4 wl = __ldg(&((const float4*)wrel)[q]);
        sr += r.x * wr.x + r.y * wr.y + r.z * wr.z + r.w * wr.w;
        st += r.x * wl.x + r.y * wl.y + r.z * wl.z + r.w * wl.w;
    }
    d_score[i] = sr + __ldg(&pb[0]);
    d_t[i] = st;
}

__global__ void k_scats1(const int* __restrict__ src, const int* __restrict__ dst) {
    int e = blockIdx.x * blockDim.x + threadIdx.x;
    if (e < Ee) atomicAdd(&d_score[dst[e]], d_t[src[e]]);
}

// ---------------- persistent top-k (4 passes + select) -------------------------
// grid barrier: ticket + spin (all blocks co-resident by construction)
__device__ __forceinline__ void gbar(unsigned* bar, unsigned target) {
    __threadfence();
    __syncthreads();
    if (threadIdx.x == 0) {
        atomicAdd(bar, 1u);
        while (*((volatile unsigned*)bar) < target) {}
    }
    __syncthreads();
    __threadfence();
}

// scan global hist (identical in every block): returns digit, updates rem
__device__ __forceinline__ int scan_hist(const unsigned* gh, int nb, int& rem,
                                         unsigned* sh, volatile int* s_io) {
    for (int b = threadIdx.x; b < nb; b += 256) sh[b] = gh[b];
    __syncthreads();
    __shared__ unsigned part[256];
    int seg = nb >> 8;
    int base = threadIdx.x * seg;
    unsigned s = 0;
    for (int v = 0; v < seg; v++) s += sh[base + v];
    part[threadIdx.x] = s;
    __syncthreads();
    if (threadIdx.x == 0) {
        unsigned cum = 0;
        int t;
        for (t = 255; t >= 0; t--) {
            if (cum + part[t] >= (unsigned)rem) break;
            cum += part[t];
        }
        s_io[0] = t;
        s_io[1] = (int)cum;
    }
    __syncthreads();
    if (threadIdx.x == s_io[0]) {
        unsigned cum = (unsigned)s_io[1];
        for (int v = seg - 1; v >= 0; v--) {
            unsigned c = sh[base + v];
            cum += c;
            if (cum >= (unsigned)rem) {
                s_io[2] = base + v;
                s_io[3] = rem - (int)(cum - c);
                break;
            }
        }
    }
    __syncthreads();
    int digit = s_io[2];
    rem = s_io[3];
    __syncthreads();
    return digit;
}

__global__ void __launch_bounds__(256, 1) k_topk1() {
    __shared__ unsigned sh[8192];
    __shared__ int s_io[4];
    const int shifts[4] = {36, 23, 10, 0};
    const int ws[4] = {13, 13, 13, 10};
    unsigned long long prefix = 0;
    int rem = Kk1;
#pragma unroll
    for (int p = 0; p < 4; p++) {
        int w = ws[p], shift = shifts[p], nb = 1 << w;
        unsigned mask = (unsigned)(nb - 1);
        for (int b = threadIdx.x; b < nb; b += 256) sh[b] = 0;
        __syncthreads();
        for (int i = blockIdx.x * 256 + threadIdx.x; i < Nn; i += G1 * 256) {
            unsigned long long key;
            if (p == 0) {
                key = ((unsigned long long)f2u(d_score[i]) << 17) |
                      (unsigned long long)(131071u - (unsigned)i);
                d_key[i] = key;
            } else key = d_key[i];
            if (p == 0 || (key >> (shift + w)) == prefix)
                atomicAdd(&sh[(unsigned)(key >> shift) & mask], 1u);
        }
        __syncthreads();
        for (int b = threadIdx.x; b < nb; b += 256)
            if (sh[b]) atomicAdd(&d_hist1[p][b], sh[b]);
        gbar(&d_bar1, (unsigned)(p + 1) * G1);
        int digit = scan_hist(d_hist1[p], nb, rem, sh, s_io);
        prefix = (prefix << w) | (unsigned long long)digit;
    }
    // select + bitmask + gather x1
    for (int i = blockIdx.x * 256 + threadIdx.x; i < Nn; i += G1 * 256) {
        if (d_key[i] >= prefix) {
            int p = atomicAdd(&d_counter, 1);
            d_perm[p] = i;
            atomicOr(&d_selbit[i >> 5], 1u << (i & 31));
            d_deg2[i] = 0;
            float th = tanhf(d_score[i]);
            const float4* h = (const float4*)&d_h[i * Hh];
            float4* o = (float4*)&d_x1[p * Hh];
#pragma unroll
            for (int q = 0; q < 4; q++) {
                float4 v = h[q];
                v.x *= th; v.y *= th; v.z *= th; v.w *= th;
                o[q] = v;
            }
        }
    }
}

__device__ __forceinline__ bool selbit(int i) {
    return (__ldg(&d_selbit[i >> 5]) >> (i & 31)) & 1u;
}

// deg2: count surviving in-edges (bitmask, L1-resident)
__global__ void k_deg2(const int* __restrict__ src, const int* __restrict__ dst) {
    int e = blockIdx.x * blockDim.x + threadIdx.x;
    if (e >= Ee) return;
    int s = src[e], d = dst[e];
    if (selbit(s) && selbit(d)) atomicAdd(&d_deg2[d], 1);
}

// conv2: dinv2 + g0 = x1@W2 + self-loop init of h2 (old-id indexed)
__global__ void k_conv2(const float* __restrict__ W2, const float* __restrict__ b2) {
    int p = blockIdx.x * blockDim.x + threadIdx.x;
    if (p >= Kk1) return;
    int i = d_perm[p];
    float di = rsqrtf((float)d_deg2[i] + 1.0f);
    d_dinv2[i] = di;
    float s = di * di;
    float xr[Hh];
    const float4* xv = (const float4*)&d_x1[p * Hh];
#pragma unroll
    for (int q = 0; q < 4; q++) {
        float4 v = xv[q];
        xr[q * 4] = v.x; xr[q * 4 + 1] = v.y; xr[q * 4 + 2] = v.z; xr[q * 4 + 3] = v.w;
    }
    float* g = &d_g0[i * 16];
    float* h2 = &d_h2[i * 16];
#pragma unroll
    for (int j = 0; j < Cc; j++) {
        float a = 0.f;
#pragma unroll
        for (int f = 0; f < Hh; f++) a += xr[f] * __ldg(&W2[f * Cc + j]);
        g[j] = a;
        h2[j] = a * s + __ldg(&b2[j]);
    }
#pragma unroll
    for (int j = Cc; j < 16; j++) { g[j] = 0.f; h2[j] = 0.f; }
}

__global__ void k_scat2(const int* __restrict__ src, const int* __restrict__ dst) {
    int e = blockIdx.x * blockDim.x + threadIdx.x;
    if (e >= Ee) return;
    int s = src[e], d = dst[e];
    if (!(selbit(s) && selbit(d))) return;
    float nrm = __ldg(&d_dinv2[s]) * __ldg(&d_dinv2[d]);
    const float4* g = (const float4*)&d_g0[s * 16];
    float* a = &d_h2[d * 16];
#pragma unroll
    for (int q = 0; q < 3; q++) {
        float4 v = g[q];
        v.x *= nrm; v.y *= nrm; v.z *= nrm; v.w *= nrm;
        red_v4(a + q * 4, v);
    }
}

__global__ void k_prep2(const float* __restrict__ wroot, const float* __restrict__ wrel,
                        const float* __restrict__ pb) {
    int p = blockIdx.x * blockDim.x + threadIdx.x;
    if (p >= Kk1) return;
    int i = d_perm[p];
    float sr = 0.f, st = 0.f;
#pragma unroll
    for (int j = 0; j < Cc; j++) {
        float v = d_h2[i * 16 + j];
        sr += v * __ldg(&wroot[j]);
        st += v * __ldg(&wrel[j]);
    }
    d_score2[i] = sr + __ldg(&pb[0]);
    d_t2[i] = st;
}

__global__ void k_scats2(const int* __restrict__ src, const int* __restrict__ dst) {
    int e = blockIdx.x * blockDim.x + threadIdx.x;
    if (e >= Ee) return;
    int s = src[e], d = dst[e];
    if (selbit(s) && selbit(d)) atomicAdd(&d_score2[d], __ldg(&d_t2[s]));
}

// topk2: 4 passes + select + mean + log_softmax
__global__ void __launch_bounds__(256, 1) k_topk2(float* __restrict__ out) {
    __shared__ unsigned sh[8192];
    __shared__ int s_io[4];
    const int shifts[4] = {34, 21, 8, 0};
    const int ws[4] = {13, 13, 13, 8};
    unsigned long long prefix = 0;
    int rem = Kk2;
#pragma unroll
    for (int p = 0; p < 4; p++) {
        int w = ws[p], shift = shifts[p], nb = 1 << w;
        unsigned mask = (unsigned)(nb - 1);
        for (int b = threadIdx.x; b < nb; b += 256) sh[b] = 0;
        __syncthreads();
        for (int i = blockIdx.x * 256 + threadIdx.x; i < Kk1; i += G2 * 256) {
            unsigned long long key;
            if (p == 0) {
                float sc = __ldg(&d_score2[d_perm[i]]);
                key = ((unsigned long long)f2u(sc) << 15) |
                      (unsigned long long)(32767u - (unsigned)i);
                d_key[i] = key;
            } else key = d_key[i];
            if (p == 0 || (key >> (shift + w)) == prefix)
                atomicAdd(&sh[(unsigned)(key >> shift) & mask], 1u);
        }
        __syncthreads();
        for (int b = threadIdx.x; b < nb; b += 256)
            if (sh[b]) atomicAdd(&d_hist2[p][b], sh[b]);
        gbar(&d_bar2, (unsigned)(p + 1) * G2);
        int digit = scan_hist(d_hist2[p], nb, rem, sh, s_io);
        prefix = (prefix << w) | (unsigned long long)digit;
    }
    // select + accumulate mean
    float acc[Cc];
#pragma unroll
    for (int j = 0; j < Cc; j++) acc[j] = 0.f;
    for (int i = blockIdx.x * 256 + threadIdx.x; i < Kk1; i += G2 * 256) {
        if (d_key[i] >= prefix) {
            int n = d_perm[i];
            float th = tanhf(d_score2[n]);
#pragma unroll
            for (int j = 0; j < Cc; j++) acc[j] += d_h2[n * 16 + j] * th;
        }
    }
#pragma unroll
    for (int o = 16; o; o >>= 1)
#pragma unroll
        for (int j = 0; j < Cc; j++) acc[j] += __shfl_xor_sync(0xFFFFFFFFu, acc[j], o);
    if ((threadIdx.x & 31) < Cc && acc[0] == acc[0]) {
        // lane j adds component j (each lane has full acc after butterfly)
    }
    if ((threadIdx.x & 31) == 0)
#pragma unroll
        for (int j = 0; j < Cc; j++) atomicAdd(&d_acc[j], acc[j]);
    __threadfence();
    __syncthreads();
    if (threadIdx.x == 0) {
        if (atomicAdd(&d_tick2, 1u) == (unsigned)G2 - 1u) {
            float m[Cc], mx = -1e30f;
#pragma unroll
            for (int j = 0; j < Cc; j++) {
                m[j] = d_acc[j] / (float)Kk2;
                mx = fmaxf(mx, m[j]);
            }
            float lse = 0.f;
#pragma unroll
            for (int j = 0; j < Cc; j++) lse += expf(m[j] - mx);
            lse = logf(lse);
#pragma unroll
            for (int j = 0; j < Cc; j++) out[j] = m[j] - mx - lse;
        }
    }
}

// ---------------- launch --------------------------------------------------------
extern "C" void kernel_launch(void* const* d_in, const int* in_sizes, int n_in,
                              void* d_out, int out_size) {
    const float* x = (const float*)d_in[0];
    const int* esrc = (const int*)d_in[1];
    const int* edst = (const int*)d_in[2];
    const float* W1 = (const float*)d_in[3];
    const float* b1 = (const float*)d_in[4];
    const float* p1wr = (const float*)d_in[5];
    const float* p1wl = (const float*)d_in[6];
    const float* p1b = (const float*)d_in[7];
    const float* W2 = (const float*)d_in[8];
    const float* b2 = (const float*)d_in[9];
    const float* p2wr = (const float*)d_in[10];
    const float* p2wl = (const float*)d_in[11];
    const float* p2b = (const float*)d_in[12];
    float* out = (float*)d_out;

    const int T = 256;
    k_init<<<(Nn * Hh + T - 1) / T, T>>>();
    k_front<<<MM1_BLOCKS + DEG_BLOCKS, T>>>(x, W1, edst);
    k_dinv<<<(Nn + T - 1) / T, T>>>();
    k_scat1<<<(Ee * 4) / T, T>>>(esrc, edst);
    k_prep1<<<(Nn + T - 1) / T, T>>>(b1, p1wr, p1wl, p1b);
    k_scats1<<<(Ee + T - 1) / T, T>>>(esrc, edst);
    k_topk1<<<G1, 256>>>();
    k_deg2<<<(Ee + T - 1) / T, T>>>(esrc, edst);
    k_conv2<<<(Kk1 + T - 1) / T, T>>>(W2, b2);
    k_scat2<<<(Ee + T - 1) / T, T>>>(esrc, edst);
    k_prep2<<<(Kk1 + T - 1) / T, T>>>(p2wr, p2wl, p2b);
    k_scats2<<<(Ee + T - 1) / T, T>>>(esrc, edst);
    k_topk2<<<G2, 256>>>(out);
}